// round 6
// baseline (speedup 1.0000x reference)
#include <cuda_runtime.h>
#include <cuda_bf16.h>

#define NN 100000
#define NE 1600000
#define D 64
#define EPS 1e-5f
#define SCAN_BLK 1024
#define NB 98                 // ceil(NN / SCAN_BLK)
#define NBLK 296              // csr_build grid: 2 blocks/SM, all resident

// Scratch (__device__ globals; zero-initialized at module load)
__device__ unsigned g_tickets;          // monotonic grid-barrier tickets
__device__ int   g_cnt[NN];
__device__ int   g_rowstart[NN + 1];
__device__ int   g_woff[NN];
__device__ int   g_blksum[NB];
__device__ int2  g_edge[NE];            // (col, val-bits), row-sorted
__device__ float g_sum[D];
__device__ float g_sq[D];

// Packed fp32x2 helpers (FFMA2 only reachable via PTX)
#define FMA2(d, a, b, c) asm("fma.rn.f32x2 %0, %1, %2, %3;" : "=l"(d) : "l"(a), "l"(b), "l"(c))
#define PACK2U(d, lo, hi) asm("mov.b64 %0, {%1, %2};" : "=l"(d) : "r"(lo), "r"(hi))
#define UNPACK2U(lo, hi, v) asm("mov.b64 {%0, %1}, %2;" : "=r"(lo), "=r"(hi) : "l"(v))

// ---------------------------------------------------------------------------
// Software grid barrier: monotonic tickets (replay-safe, no reset needed).
// Requires all NBLK blocks resident (guaranteed by __launch_bounds__(1024,2)).
// ---------------------------------------------------------------------------
__device__ __forceinline__ void grid_barrier() {
    __syncthreads();
    if (threadIdx.x == 0) {
        __threadfence();
        unsigned t = atomicAdd(&g_tickets, 1u) + 1u;
        unsigned target = ((t + NBLK - 1u) / NBLK) * NBLK;
        while (*(volatile unsigned*)&g_tickets < target) { }
        __threadfence();
    }
    __syncthreads();
}

// ---------------------------------------------------------------------------
// One-kernel CSR build: hist -> local scan -> block offsets -> scatter
// ---------------------------------------------------------------------------
__global__ void __launch_bounds__(SCAN_BLK, 2) csr_build_kernel(
        const float* __restrict__ val,
        const int*   __restrict__ row,
        const int*   __restrict__ col) {
    const int tid = threadIdx.x;
    const int bid = blockIdx.x;
    const int gtid = bid * SCAN_BLK + tid;
    const int nthreads = NBLK * SCAN_BLK;           // 303k

    // Phase 1: histogram, 8 edges per iteration (g_cnt zeroed by prev call)
    for (int t = gtid; t < NE / 8; t += nthreads) {
        int4 ra = ((const int4*)row)[2 * t];
        int4 rb = ((const int4*)row)[2 * t + 1];
        atomicAdd(&g_cnt[ra.x], 1);
        atomicAdd(&g_cnt[ra.y], 1);
        atomicAdd(&g_cnt[ra.z], 1);
        atomicAdd(&g_cnt[ra.w], 1);
        atomicAdd(&g_cnt[rb.x], 1);
        atomicAdd(&g_cnt[rb.y], 1);
        atomicAdd(&g_cnt[rb.z], 1);
        atomicAdd(&g_cnt[rb.w], 1);
    }
    if (bid == 0 && tid < D) { g_sum[tid] = 0.f; g_sq[tid] = 0.f; }

    grid_barrier();

    // Phase 2: per-chunk exclusive scan (first NB blocks); zero g_cnt for next call
    if (bid < NB) {
        int i = bid * SCAN_BLK + tid;
        int v = (i < NN) ? g_cnt[i] : 0;
        if (i < NN) g_cnt[i] = 0;
        int lane = tid & 31, w = tid >> 5;
        int s = v;
        #pragma unroll
        for (int d = 1; d < 32; d <<= 1) {
            int t = __shfl_up_sync(0xFFFFFFFFu, s, d);
            if (lane >= d) s += t;
        }
        __shared__ int wsum[32];
        if (lane == 31) wsum[w] = s;
        __syncthreads();
        if (w == 0) {
            int ws = wsum[lane];
            #pragma unroll
            for (int d = 1; d < 32; d <<= 1) {
                int t = __shfl_up_sync(0xFFFFFFFFu, ws, d);
                if (lane >= d) ws += t;
            }
            wsum[lane] = ws;
        }
        __syncthreads();
        int incl = s + (w > 0 ? wsum[w - 1] : 0);
        if (i < NN) g_rowstart[i] = incl - v;      // chunk-local exclusive
        if (tid == SCAN_BLK - 1) g_blksum[bid] = incl;
    }

    grid_barrier();

    // Phase 3: add block offsets, init write cursors
    if (bid < NB) {
        __shared__ int bsum[NB];
        __shared__ int boff_sh;
        if (tid < NB) bsum[tid] = g_blksum[tid];
        __syncthreads();
        if (tid == 0) {
            int o = 0;
            for (int k = 0; k < bid; k++) o += bsum[k];
            boff_sh = o;
        }
        __syncthreads();
        int i = bid * SCAN_BLK + tid;
        if (i < NN) {
            int rv = g_rowstart[i] + boff_sh;
            g_rowstart[i] = rv;
            g_woff[i] = rv;
        }
    }
    if (bid == 0 && tid == 0) g_rowstart[NN] = NE;

    grid_barrier();

    // Phase 4: scatter, 8 independent atomic chains per iteration
    for (int t = gtid; t < NE / 8; t += nthreads) {
        int4   ra = ((const int4*)row)[2 * t];
        int4   rb = ((const int4*)row)[2 * t + 1];
        int4   ca = ((const int4*)col)[2 * t];
        int4   cb = ((const int4*)col)[2 * t + 1];
        float4 va = ((const float4*)val)[2 * t];
        float4 vb = ((const float4*)val)[2 * t + 1];
        int p0 = atomicAdd(&g_woff[ra.x], 1);
        int p1 = atomicAdd(&g_woff[ra.y], 1);
        int p2 = atomicAdd(&g_woff[ra.z], 1);
        int p3 = atomicAdd(&g_woff[ra.w], 1);
        int p4 = atomicAdd(&g_woff[rb.x], 1);
        int p5 = atomicAdd(&g_woff[rb.y], 1);
        int p6 = atomicAdd(&g_woff[rb.z], 1);
        int p7 = atomicAdd(&g_woff[rb.w], 1);
        g_edge[p0] = make_int2(ca.x, __float_as_int(va.x));
        g_edge[p1] = make_int2(ca.y, __float_as_int(va.y));
        g_edge[p2] = make_int2(ca.z, __float_as_int(va.z));
        g_edge[p3] = make_int2(ca.w, __float_as_int(va.w));
        g_edge[p4] = make_int2(cb.x, __float_as_int(vb.x));
        g_edge[p5] = make_int2(cb.y, __float_as_int(vb.y));
        g_edge[p6] = make_int2(cb.z, __float_as_int(vb.z));
        g_edge[p7] = make_int2(cb.w, __float_as_int(vb.w));
    }
}

// ---------------------------------------------------------------------------
// Fused: h = A@x (CSR gather, 8 rows/warp) ; y = h@W^T + x ; BN stats.
// Bias b dropped: BN with batch stats is invariant to constant column shift.
// ---------------------------------------------------------------------------
__global__ void __launch_bounds__(256) fused_kernel(const float* __restrict__ x,
                                                    const float* __restrict__ W,
                                                    float* __restrict__ y) {
    // Wp[p*32+l] = (Wt[2p][2l], Wt[2p][2l+1], Wt[2p+1][2l], Wt[2p+1][2l+1]),
    // Wt[k][j] = W[j*D+k]
    __shared__ float4 Wp[32 * 32];     // 16KB
    __shared__ float4 Hs[8][160];      // padded: logical 128 float4 per warp
    __shared__ float  rs[D];
    __shared__ float  rq[D];

    int tid = threadIdx.x;
    for (int idx = tid; idx < 1024; idx += 256) {
        int p = idx >> 5, l = idx & 31;
        Wp[idx] = make_float4(W[(2 * l) * D + 2 * p],     W[(2 * l + 1) * D + 2 * p],
                              W[(2 * l) * D + 2 * p + 1], W[(2 * l + 1) * D + 2 * p + 1]);
    }
    if (tid < D) { rs[tid] = 0.f; rq[tid] = 0.f; }
    __syncthreads();

    int w = tid >> 5;
    int lane = tid & 31;
    const unsigned long long* xb8 = (const unsigned long long*)x;  // (x[2l],x[2l+1])
    const ulonglong2* Wp2 = (const ulonglong2*)Wp;
    float4* Hw = Hs[w];

    float s0 = 0.f, s1 = 0.f, q0 = 0.f, q1 = 0.f;
    const int ngroups = NN / 8;        // 12500

    for (int g = blockIdx.x * 8 + w; g < ngroups; g += gridDim.x * 8) {
        int r0 = g * 8;

        // --- gather 8 rows; lane accumulates its 2 columns per row ---
        float hx[8], hy[8];
        #pragma unroll
        for (int rr = 0; rr < 8; rr++) {
            int r = r0 + rr;
            int start = g_rowstart[r];
            int end   = g_rowstart[r + 1];
            unsigned long long hp = 0ull;            // packed (hx,hy)
            int j = start;
            int end8 = start + ((end - start) & ~7);
            for (; j < end8; j += 8) {
                int2 e[8];
                #pragma unroll
                for (int u = 0; u < 8; u++) e[u] = g_edge[j + u];
                unsigned long long xv[8];
                #pragma unroll
                for (int u = 0; u < 8; u++)
                    xv[u] = xb8[(size_t)e[u].x * 32 + lane];
                #pragma unroll
                for (int u = 0; u < 8; u++) {
                    unsigned long long vv;
                    PACK2U(vv, e[u].y, e[u].y);
                    FMA2(hp, vv, xv[u], hp);
                }
            }
            for (; j < end; j++) {
                int2 e0 = g_edge[j];
                unsigned long long x0 = xb8[(size_t)e0.x * 32 + lane];
                unsigned long long vv;
                PACK2U(vv, e0.y, e0.y);
                FMA2(hp, vv, x0, hp);
            }
            unsigned ulo, uhi;
            UNPACK2U(ulo, uhi, hp);
            hx[rr] = __uint_as_float(ulo);
            hy[rr] = __uint_as_float(uhi);
        }
        // transpose: logical Hw[2k]=rows0-3 of col k, Hw[2k+1]=rows4-7
        Hw[5 * lane + 0] = make_float4(hx[0], hx[1], hx[2], hx[3]);  // col 2l, r0-3
        Hw[5 * lane + 1] = make_float4(hx[4], hx[5], hx[6], hx[7]);  // col 2l, r4-7
        Hw[5 * lane + 2] = make_float4(hy[0], hy[1], hy[2], hy[3]);  // col 2l+1
        Hw[5 * lane + 3] = make_float4(hy[4], hy[5], hy[6], hy[7]);
        __syncwarp();

        // --- GEMM: acc[r] = packed cols (2l, 2l+1) of output row r0+r ---
        unsigned long long acc[8];
        #pragma unroll
        for (int rr = 0; rr < 8; rr++)
            acc[rr] = xb8[(size_t)(r0 + rr) * 32 + lane];   // residual seed

        #pragma unroll
        for (int p = 0; p < 32; p++) {
            ulonglong2 wv = Wp2[p * 32 + lane];   // .x: k=2p pair, .y: k=2p+1 pair
            float4 alo = Hw[5 * p + 0];           // col 2p,   rows 0-3
            float4 ahi = Hw[5 * p + 1];           // col 2p,   rows 4-7
            float4 blo = Hw[5 * p + 2];           // col 2p+1, rows 0-3
            float4 bhi = Hw[5 * p + 3];           // col 2p+1, rows 4-7
            unsigned long long dd;
            unsigned u;
            u = __float_as_uint(alo.x); PACK2U(dd, u, u); FMA2(acc[0], dd, wv.x, acc[0]);
            u = __float_as_uint(blo.x); PACK2U(dd, u, u); FMA2(acc[0], dd, wv.y, acc[0]);
            u = __float_as_uint(alo.y); PACK2U(dd, u, u); FMA2(acc[1], dd, wv.x, acc[1]);
            u = __float_as_uint(blo.y); PACK2U(dd, u, u); FMA2(acc[1], dd, wv.y, acc[1]);
            u = __float_as_uint(alo.z); PACK2U(dd, u, u); FMA2(acc[2], dd, wv.x, acc[2]);
            u = __float_as_uint(blo.z); PACK2U(dd, u, u); FMA2(acc[2], dd, wv.y, acc[2]);
            u = __float_as_uint(alo.w); PACK2U(dd, u, u); FMA2(acc[3], dd, wv.x, acc[3]);
            u = __float_as_uint(blo.w); PACK2U(dd, u, u); FMA2(acc[3], dd, wv.y, acc[3]);
            u = __float_as_uint(ahi.x); PACK2U(dd, u, u); FMA2(acc[4], dd, wv.x, acc[4]);
            u = __float_as_uint(bhi.x); PACK2U(dd, u, u); FMA2(acc[4], dd, wv.y, acc[4]);
            u = __float_as_uint(ahi.y); PACK2U(dd, u, u); FMA2(acc[5], dd, wv.x, acc[5]);
            u = __float_as_uint(bhi.y); PACK2U(dd, u, u); FMA2(acc[5], dd, wv.y, acc[5]);
            u = __float_as_uint(ahi.z); PACK2U(dd, u, u); FMA2(acc[6], dd, wv.x, acc[6]);
            u = __float_as_uint(bhi.z); PACK2U(dd, u, u); FMA2(acc[6], dd, wv.y, acc[6]);
            u = __float_as_uint(ahi.w); PACK2U(dd, u, u); FMA2(acc[7], dd, wv.x, acc[7]);
            u = __float_as_uint(bhi.w); PACK2U(dd, u, u); FMA2(acc[7], dd, wv.y, acc[7]);
        }

        #pragma unroll
        for (int rr = 0; rr < 8; rr++) {
            unsigned ulo, uhi;
            UNPACK2U(ulo, uhi, acc[rr]);
            float o0 = __uint_as_float(ulo);
            float o1 = __uint_as_float(uhi);
            ((float2*)y)[(size_t)(r0 + rr) * 32 + lane] = make_float2(o0, o1);
            s0 += o0; s1 += o1;
            q0 = fmaf(o0, o0, q0);
            q1 = fmaf(o1, o1, q1);
        }
        __syncwarp();
    }

    atomicAdd(&rs[2 * lane],     s0);
    atomicAdd(&rs[2 * lane + 1], s1);
    atomicAdd(&rq[2 * lane],     q0);
    atomicAdd(&rq[2 * lane + 1], q1);
    __syncthreads();
    if (tid < D) {
        atomicAdd(&g_sum[tid], rs[tid]);
        atomicAdd(&g_sq[tid],  rq[tid]);
    }
}

// ---------------------------------------------------------------------------
// BatchNorm + ReLU in-place, 4 strided float4 per thread (MLP 4)
// ---------------------------------------------------------------------------
__global__ void bn_kernel(const float* __restrict__ gamma,
                          const float* __restrict__ beta,
                          float* __restrict__ y) {
    __shared__ float sc[D];
    __shared__ float sh[D];
    int tid = threadIdx.x;
    if (tid < D) {
        const float invN = 1.0f / (float)NN;
        float mean = g_sum[tid] * invN;
        float var  = g_sq[tid] * invN - mean * mean;
        float s = gamma[tid] * rsqrtf(var + EPS);
        sc[tid] = s;
        sh[tid] = beta[tid] - mean * s;
    }
    __syncthreads();

    const int total4 = NN * D / 4;                 // 1.6M
    const int stride = gridDim.x * blockDim.x;
    int idx = blockIdx.x * blockDim.x + threadIdx.x;

    float4 v[4];
    int id[4];
    #pragma unroll
    for (int u = 0; u < 4; u++) {
        id[u] = idx + u * stride;
        if (id[u] < total4) v[u] = ((float4*)y)[id[u]];
    }
    #pragma unroll
    for (int u = 0; u < 4; u++) {
        if (id[u] < total4) {
            int c = (id[u] * 4) & 63;
            float4 t = v[u];
            t.x = fmaxf(fmaf(t.x, sc[c],     sh[c]),     0.f);
            t.y = fmaxf(fmaf(t.y, sc[c + 1], sh[c + 1]), 0.f);
            t.z = fmaxf(fmaf(t.z, sc[c + 2], sh[c + 2]), 0.f);
            t.w = fmaxf(fmaf(t.w, sc[c + 3], sh[c + 3]), 0.f);
            ((float4*)y)[id[u]] = t;
        }
    }
}

// ---------------------------------------------------------------------------
// Launch. Input order: x, adj_val, W, b, gamma, beta, adj_row, adj_col
// ---------------------------------------------------------------------------
extern "C" void kernel_launch(void* const* d_in, const int* in_sizes, int n_in,
                              void* d_out, int out_size) {
    const float* x       = (const float*)d_in[0];
    const float* adj_val = (const float*)d_in[1];
    const float* W       = (const float*)d_in[2];
    const float* gamma   = (const float*)d_in[4];
    const float* beta    = (const float*)d_in[5];
    const int*   adj_row = (const int*)d_in[6];
    const int*   adj_col = (const int*)d_in[7];
    float* y = (float*)d_out;

    csr_build_kernel<<<NBLK, SCAN_BLK>>>(adj_val, adj_row, adj_col);
    fused_kernel<<<1184, 256>>>(x, W, y);
    {
        int total4 = NN * D / 4;
        int blocks = (total4 / 4 + 255) / 256;     // 4 float4 per thread
        bn_kernel<<<blocks, 256>>>(gamma, beta, y);
    }
}

// round 10
// speedup vs baseline: 1.0600x; 1.0600x over previous
#include <cuda_runtime.h>
#include <cuda_bf16.h>

#define NN 100000
#define NE 1600000
#define D 64
#define EPS 1e-5f
#define SCAN_BLK 1024
#define NB 98                 // ceil(NN / SCAN_BLK)
#define NBLK 148              // csr_build grid: 1 block/SM, all resident

// Scratch (__device__ globals; zero-initialized at module load)
__device__ unsigned g_tickets;          // monotonic grid-barrier tickets
__device__ int   g_cnt[NN];
__device__ int   g_rowstart[NN + 1];
__device__ int   g_woff[NN];
__device__ int   g_blksum[NB];
__device__ int2  g_edge[NE];            // (col, val-bits), row-sorted
__device__ float g_sum[D];
__device__ float g_sq[D];

// Packed fp32x2 helpers (FFMA2 only reachable via PTX)
#define FMA2(d, a, b, c) asm("fma.rn.f32x2 %0, %1, %2, %3;" : "=l"(d) : "l"(a), "l"(b), "l"(c))
#define PACK2U(d, lo, hi) asm("mov.b64 %0, {%1, %2};" : "=l"(d) : "r"(lo), "r"(hi))
#define UNPACK2U(lo, hi, v) asm("mov.b64 {%0, %1}, %2;" : "=r"(lo), "=r"(hi) : "l"(v))

// ---------------------------------------------------------------------------
// Software grid barrier: monotonic tickets (replay-safe, no reset needed).
// Requires all NBLK blocks resident (148 blocks x 1024 thr = 1 block/SM).
// ---------------------------------------------------------------------------
__device__ __forceinline__ void grid_barrier() {
    __syncthreads();
    if (threadIdx.x == 0) {
        __threadfence();
        unsigned t = atomicAdd(&g_tickets, 1u) + 1u;
        unsigned target = ((t + NBLK - 1u) / NBLK) * NBLK;
        while (*(volatile unsigned*)&g_tickets < target) { }
        __threadfence();
    }
    __syncthreads();
}

// ---------------------------------------------------------------------------
// One-kernel CSR build: hist -> local scan -> block offsets -> scatter.
// Phases 1 & 4 process 16 edges/thread (4 x int4) for max MLP: with
// 148*1024 = 151k threads and NE/16 = 100k tiles, each thread does <= 1 tile.
// ---------------------------------------------------------------------------
__global__ void __launch_bounds__(SCAN_BLK) csr_build_kernel(
        const float* __restrict__ val,
        const int*   __restrict__ row,
        const int*   __restrict__ col) {
    const int tid = threadIdx.x;
    const int bid = blockIdx.x;
    const int gtid = bid * SCAN_BLK + tid;
    const int nthreads = NBLK * SCAN_BLK;           // 151552

    // Phase 1: histogram, 16 edges per thread (g_cnt zeroed by prev call)
    for (int t = gtid; t < NE / 16; t += nthreads) {
        int4 r[4];
        #pragma unroll
        for (int u = 0; u < 4; u++) r[u] = ((const int4*)row)[4 * t + u];
        #pragma unroll
        for (int u = 0; u < 4; u++) {
            atomicAdd(&g_cnt[r[u].x], 1);
            atomicAdd(&g_cnt[r[u].y], 1);
            atomicAdd(&g_cnt[r[u].z], 1);
            atomicAdd(&g_cnt[r[u].w], 1);
        }
    }
    if (bid == 0 && tid < D) { g_sum[tid] = 0.f; g_sq[tid] = 0.f; }

    grid_barrier();

    // Phase 2: per-chunk exclusive scan (first NB blocks); zero g_cnt for next call
    if (bid < NB) {
        int i = bid * SCAN_BLK + tid;
        int v = (i < NN) ? g_cnt[i] : 0;
        if (i < NN) g_cnt[i] = 0;
        int lane = tid & 31, w = tid >> 5;
        int s = v;
        #pragma unroll
        for (int d = 1; d < 32; d <<= 1) {
            int t = __shfl_up_sync(0xFFFFFFFFu, s, d);
            if (lane >= d) s += t;
        }
        __shared__ int wsum[32];
        if (lane == 31) wsum[w] = s;
        __syncthreads();
        if (w == 0) {
            int ws = wsum[lane];
            #pragma unroll
            for (int d = 1; d < 32; d <<= 1) {
                int t = __shfl_up_sync(0xFFFFFFFFu, ws, d);
                if (lane >= d) ws += t;
            }
            wsum[lane] = ws;
        }
        __syncthreads();
        int incl = s + (w > 0 ? wsum[w - 1] : 0);
        if (i < NN) g_rowstart[i] = incl - v;      // chunk-local exclusive
        if (tid == SCAN_BLK - 1) g_blksum[bid] = incl;
    }

    grid_barrier();

    // Phase 3: add block offsets, init write cursors
    if (bid < NB) {
        __shared__ int bsum[NB];
        __shared__ int boff_sh;
        if (tid < NB) bsum[tid] = g_blksum[tid];
        __syncthreads();
        if (tid == 0) {
            int o = 0;
            for (int k = 0; k < bid; k++) o += bsum[k];
            boff_sh = o;
        }
        __syncthreads();
        int i = bid * SCAN_BLK + tid;
        if (i < NN) {
            int rv = g_rowstart[i] + boff_sh;
            g_rowstart[i] = rv;
            g_woff[i] = rv;
        }
    }
    if (bid == 0 && tid == 0) g_rowstart[NN] = NE;

    grid_barrier();

    // Phase 4: scatter, 16 edges per thread (16 independent atomic chains)
    for (int t = gtid; t < NE / 16; t += nthreads) {
        int4   r[4], c[4];
        float4 v[4];
        #pragma unroll
        for (int u = 0; u < 4; u++) {
            r[u] = ((const int4*)row)[4 * t + u];
            c[u] = ((const int4*)col)[4 * t + u];
            v[u] = ((const float4*)val)[4 * t + u];
        }
        int p[16];
        #pragma unroll
        for (int u = 0; u < 4; u++) {
            p[4 * u + 0] = atomicAdd(&g_woff[r[u].x], 1);
            p[4 * u + 1] = atomicAdd(&g_woff[r[u].y], 1);
            p[4 * u + 2] = atomicAdd(&g_woff[r[u].z], 1);
            p[4 * u + 3] = atomicAdd(&g_woff[r[u].w], 1);
        }
        #pragma unroll
        for (int u = 0; u < 4; u++) {
            g_edge[p[4 * u + 0]] = make_int2(c[u].x, __float_as_int(v[u].x));
            g_edge[p[4 * u + 1]] = make_int2(c[u].y, __float_as_int(v[u].y));
            g_edge[p[4 * u + 2]] = make_int2(c[u].z, __float_as_int(v[u].z));
            g_edge[p[4 * u + 3]] = make_int2(c[u].w, __float_as_int(v[u].w));
        }
    }
}

// ---------------------------------------------------------------------------
// Fused: h = A@x (CSR gather, 8 rows/warp) ; y = h@W^T + x ; BN stats.
// Bias b dropped: BN with batch stats is invariant to constant column shift.
// ---------------------------------------------------------------------------
__global__ void __launch_bounds__(256) fused_kernel(const float* __restrict__ x,
                                                    const float* __restrict__ W,
                                                    float* __restrict__ y) {
    // Wp[p*32+l] = (Wt[2p][2l], Wt[2p][2l+1], Wt[2p+1][2l], Wt[2p+1][2l+1])
    __shared__ float4 Wp[32 * 32];     // 16KB
    __shared__ float4 Hs[8][160];      // padded: logical 128 float4 per warp
    __shared__ float  rs[D];
    __shared__ float  rq[D];

    int tid = threadIdx.x;
    for (int idx = tid; idx < 1024; idx += 256) {
        int p = idx >> 5, l = idx & 31;
        Wp[idx] = make_float4(W[(2 * l) * D + 2 * p],     W[(2 * l + 1) * D + 2 * p],
                              W[(2 * l) * D + 2 * p + 1], W[(2 * l + 1) * D + 2 * p + 1]);
    }
    if (tid < D) { rs[tid] = 0.f; rq[tid] = 0.f; }
    __syncthreads();

    int w = tid >> 5;
    int lane = tid & 31;
    const unsigned long long* xb8 = (const unsigned long long*)x;  // (x[2l],x[2l+1])
    const ulonglong2* Wp2 = (const ulonglong2*)Wp;
    float4* Hw = Hs[w];

    float s0 = 0.f, s1 = 0.f, q0 = 0.f, q1 = 0.f;
    const int ngroups = NN / 8;        // 12500

    for (int g = blockIdx.x * 8 + w; g < ngroups; g += gridDim.x * 8) {
        int r0 = g * 8;

        // --- gather 8 rows; lane accumulates its 2 columns per row ---
        float hx[8], hy[8];
        #pragma unroll
        for (int rr = 0; rr < 8; rr++) {
            int r = r0 + rr;
            int start = g_rowstart[r];
            int end   = g_rowstart[r + 1];
            unsigned long long hp = 0ull;            // packed (hx,hy)
            int j = start;
            int end8 = start + ((end - start) & ~7);
            for (; j < end8; j += 8) {
                int2 e[8];
                #pragma unroll
                for (int u = 0; u < 8; u++) e[u] = g_edge[j + u];
                unsigned long long xv[8];
                #pragma unroll
                for (int u = 0; u < 8; u++)
                    xv[u] = xb8[(size_t)e[u].x * 32 + lane];
                #pragma unroll
                for (int u = 0; u < 8; u++) {
                    unsigned long long vv;
                    PACK2U(vv, e[u].y, e[u].y);
                    FMA2(hp, vv, xv[u], hp);
                }
            }
            for (; j < end; j++) {
                int2 e0 = g_edge[j];
                unsigned long long x0 = xb8[(size_t)e0.x * 32 + lane];
                unsigned long long vv;
                PACK2U(vv, e0.y, e0.y);
                FMA2(hp, vv, x0, hp);
            }
            unsigned ulo, uhi;
            UNPACK2U(ulo, uhi, hp);
            hx[rr] = __uint_as_float(ulo);
            hy[rr] = __uint_as_float(uhi);
        }
        // transpose: logical Hw[2k]=rows0-3 of col k, Hw[2k+1]=rows4-7
        Hw[5 * lane + 0] = make_float4(hx[0], hx[1], hx[2], hx[3]);  // col 2l, r0-3
        Hw[5 * lane + 1] = make_float4(hx[4], hx[5], hx[6], hx[7]);  // col 2l, r4-7
        Hw[5 * lane + 2] = make_float4(hy[0], hy[1], hy[2], hy[3]);  // col 2l+1
        Hw[5 * lane + 3] = make_float4(hy[4], hy[5], hy[6], hy[7]);
        __syncwarp();

        // --- GEMM: acc[r] = packed cols (2l, 2l+1) of output row r0+r ---
        unsigned long long acc[8];
        #pragma unroll
        for (int rr = 0; rr < 8; rr++)
            acc[rr] = xb8[(size_t)(r0 + rr) * 32 + lane];   // residual seed

        #pragma unroll
        for (int p = 0; p < 32; p++) {
            ulonglong2 wv = Wp2[p * 32 + lane];   // .x: k=2p pair, .y: k=2p+1 pair
            float4 alo = Hw[5 * p + 0];
            float4 ahi = Hw[5 * p + 1];
            float4 blo = Hw[5 * p + 2];
            float4 bhi = Hw[5 * p + 3];
            unsigned long long dd;
            unsigned u;
            u = __float_as_uint(alo.x); PACK2U(dd, u, u); FMA2(acc[0], dd, wv.x, acc[0]);
            u = __float_as_uint(blo.x); PACK2U(dd, u, u); FMA2(acc[0], dd, wv.y, acc[0]);
            u = __float_as_uint(alo.y); PACK2U(dd, u, u); FMA2(acc[1], dd, wv.x, acc[1]);
            u = __float_as_uint(blo.y); PACK2U(dd, u, u); FMA2(acc[1], dd, wv.y, acc[1]);
            u = __float_as_uint(alo.z); PACK2U(dd, u, u); FMA2(acc[2], dd, wv.x, acc[2]);
            u = __float_as_uint(blo.z); PACK2U(dd, u, u); FMA2(acc[2], dd, wv.y, acc[2]);
            u = __float_as_uint(alo.w); PACK2U(dd, u, u); FMA2(acc[3], dd, wv.x, acc[3]);
            u = __float_as_uint(blo.w); PACK2U(dd, u, u); FMA2(acc[3], dd, wv.y, acc[3]);
            u = __float_as_uint(ahi.x); PACK2U(dd, u, u); FMA2(acc[4], dd, wv.x, acc[4]);
            u = __float_as_uint(bhi.x); PACK2U(dd, u, u); FMA2(acc[4], dd, wv.y, acc[4]);
            u = __float_as_uint(ahi.y); PACK2U(dd, u, u); FMA2(acc[5], dd, wv.x, acc[5]);
            u = __float_as_uint(bhi.y); PACK2U(dd, u, u); FMA2(acc[5], dd, wv.y, acc[5]);
            u = __float_as_uint(ahi.z); PACK2U(dd, u, u); FMA2(acc[6], dd, wv.x, acc[6]);
            u = __float_as_uint(bhi.z); PACK2U(dd, u, u); FMA2(acc[6], dd, wv.y, acc[6]);
            u = __float_as_uint(ahi.w); PACK2U(dd, u, u); FMA2(acc[7], dd, wv.x, acc[7]);
            u = __float_as_uint(bhi.w); PACK2U(dd, u, u); FMA2(acc[7], dd, wv.y, acc[7]);
        }

        #pragma unroll
        for (int rr = 0; rr < 8; rr++) {
            unsigned ulo, uhi;
            UNPACK2U(ulo, uhi, acc[rr]);
            float o0 = __uint_as_float(ulo);
            float o1 = __uint_as_float(uhi);
            ((float2*)y)[(size_t)(r0 + rr) * 32 + lane] = make_float2(o0, o1);
            s0 += o0; s1 += o1;
            q0 = fmaf(o0, o0, q0);
            q1 = fmaf(o1, o1, q1);
        }
        __syncwarp();
    }

    atomicAdd(&rs[2 * lane],     s0);
    atomicAdd(&rs[2 * lane + 1], s1);
    atomicAdd(&rq[2 * lane],     q0);
    atomicAdd(&rq[2 * lane + 1], q1);
    __syncthreads();
    if (tid < D) {
        atomicAdd(&g_sum[tid], rs[tid]);
        atomicAdd(&g_sq[tid],  rq[tid]);
    }
}

// ---------------------------------------------------------------------------
// BatchNorm + ReLU in-place, 4 strided float4 per thread (MLP 4)
// ---------------------------------------------------------------------------
__global__ void bn_kernel(const float* __restrict__ gamma,
                          const float* __restrict__ beta,
                          float* __restrict__ y) {
    __shared__ float sc[D];
    __shared__ float sh[D];
    int tid = threadIdx.x;
    if (tid < D) {
        const float invN = 1.0f / (float)NN;
        float mean = g_sum[tid] * invN;
        float var  = g_sq[tid] * invN - mean * mean;
        float s = gamma[tid] * rsqrtf(var + EPS);
        sc[tid] = s;
        sh[tid] = beta[tid] - mean * s;
    }
    __syncthreads();

    const int total4 = NN * D / 4;                 // 1.6M
    const int stride = gridDim.x * blockDim.x;
    int idx = blockIdx.x * blockDim.x + threadIdx.x;

    float4 v[4];
    int id[4];
    #pragma unroll
    for (int u = 0; u < 4; u++) {
        id[u] = idx + u * stride;
        if (id[u] < total4) v[u] = ((float4*)y)[id[u]];
    }
    #pragma unroll
    for (int u = 0; u < 4; u++) {
        if (id[u] < total4) {
            int c = (id[u] * 4) & 63;
            float4 t = v[u];
            t.x = fmaxf(fmaf(t.x, sc[c],     sh[c]),     0.f);
            t.y = fmaxf(fmaf(t.y, sc[c + 1], sh[c + 1]), 0.f);
            t.z = fmaxf(fmaf(t.z, sc[c + 2], sh[c + 2]), 0.f);
            t.w = fmaxf(fmaf(t.w, sc[c + 3], sh[c + 3]), 0.f);
            ((float4*)y)[id[u]] = t;
        }
    }
}

// ---------------------------------------------------------------------------
// Launch. Input order: x, adj_val, W, b, gamma, beta, adj_row, adj_col
// ---------------------------------------------------------------------------
extern "C" void kernel_launch(void* const* d_in, const int* in_sizes, int n_in,
                              void* d_out, int out_size) {
    const float* x       = (const float*)d_in[0];
    const float* adj_val = (const float*)d_in[1];
    const float* W       = (const float*)d_in[2];
    const float* gamma   = (const float*)d_in[4];
    const float* beta    = (const float*)d_in[5];
    const int*   adj_row = (const int*)d_in[6];
    const int*   adj_col = (const int*)d_in[7];
    float* y = (float*)d_out;

    csr_build_kernel<<<NBLK, SCAN_BLK>>>(adj_val, adj_row, adj_col);
    fused_kernel<<<592, 256>>>(x, W, y);
    {
        int total4 = NN * D / 4;
        int blocks = (total4 / 4 + 255) / 256;     // 4 float4 per thread
        bn_kernel<<<blocks, 256>>>(gamma, beta, y);
    }
}